// round 8
// baseline (speedup 1.0000x reference)
#include <cuda_runtime.h>
#include <math.h>

#define S 8192
#define D 2048
#define WSTRIDE 4096           // W row stride (2*D)
#define NCTA_REC 128
#define ROWS_PER_CTA 16        // D / NCTA_REC
#define NCHUNK 64
#define CHUNK 128              // S / NCHUNK
#define REC_THREADS 512
#define FLAG_STRIDE 32         // ints; one 128B L2 line per flag

typedef unsigned long long ull;

// ---- scratch (no runtime allocation allowed) ----
__device__ float g_hc[(size_t)S * D];        // cummax result
__device__ float g_cp[(size_t)S * D];        // ctx_proj result
__device__ float g_chunkmax[NCHUNK * D];     // cummax phase-B scratch
__device__ int   g_flagv[NCTA_REC * FLAG_STRIDE];  // padded per-CTA counters

#define NEG_INF __int_as_float(0xff800000)

// ---- packed f32x2 helpers ----
__device__ __forceinline__ ull ffma2(ull a, ull b, ull c) {
    ull d;
    asm("fma.rn.f32x2 %0, %1, %2, %3;" : "=l"(d) : "l"(a), "l"(b), "l"(c));
    return d;
}
__device__ __forceinline__ ull pack2(unsigned int lo, unsigned int hi) {
    ull v;
    asm("mov.b64 %0, {%1, %2};" : "=l"(v) : "r"(lo), "r"(hi));
    return v;
}
__device__ __forceinline__ ull pack2f(float x, float y) {
    ull v;
    asm("mov.b64 %0, {%1, %2};" : "=l"(v) : "f"(x), "f"(y));
    return v;
}
__device__ __forceinline__ ull dup2f(float x) {
    ull v;
    asm("mov.b64 %0, {%1, %1};" : "=l"(v) : "f"(x));
    return v;
}
__device__ __forceinline__ float2 unpack2(ull v) {
    float2 r;
    asm("mov.b64 {%0, %1}, %2;" : "=f"(r.x), "=f"(r.y) : "l"(v));
    return r;
}

// ---- fence-free acquire/release primitives (NO atomics) ----
__device__ __forceinline__ int ld_acquire_gpu(const int* p) {
    int v;
    asm volatile("ld.acquire.gpu.global.s32 %0, [%1];" : "=r"(v) : "l"(p) : "memory");
    return v;
}
__device__ __forceinline__ void st_release_gpu(int* p, int v) {
    asm volatile("st.release.gpu.global.s32 [%0], %1;" :: "l"(p), "r"(v) : "memory");
}

// ============================================================
// flag reset (graph replays must start from zeroed counters)
// ============================================================
__global__ void zero_flags_kernel() {
    int idx = blockIdx.x * blockDim.x + threadIdx.x;
    if (idx < NCTA_REC * FLAG_STRIDE) g_flagv[idx] = 0;
}

// ============================================================
// cummax phase A: per-(chunk, col) max
// ============================================================
__global__ void cummax_chunk_kernel(const float* __restrict__ ce) {
    int col = blockIdx.x * blockDim.x + threadIdx.x;
    int chunk = blockIdx.y;
    const float* p = ce + (size_t)chunk * CHUNK * D + col;
    float m = NEG_INF;
#pragma unroll 8
    for (int r = 0; r < CHUNK; r++) {
        m = fmaxf(m, p[(size_t)r * D]);
    }
    g_chunkmax[chunk * D + col] = m;
}

// ============================================================
// cummax phase B: exclusive prefix-max over chunks, per column
// ============================================================
__global__ void cummax_scan_kernel() {
    int col = blockIdx.x * blockDim.x + threadIdx.x;
    float run = NEG_INF;
    for (int ch = 0; ch < NCHUNK; ch++) {
        float v = g_chunkmax[ch * D + col];
        g_chunkmax[ch * D + col] = run;   // exclusive prefix
        run = fmaxf(run, v);
    }
}

// ============================================================
// cummax phase C: inclusive scan within chunk seeded by prefix
// ============================================================
__global__ void cummax_write_kernel(const float* __restrict__ ce) {
    int col = blockIdx.x * blockDim.x + threadIdx.x;
    int chunk = blockIdx.y;
    float m = g_chunkmax[chunk * D + col];
    const float* p = ce + (size_t)chunk * CHUNK * D + col;
    float*       q = g_hc + (size_t)chunk * CHUNK * D + col;
#pragma unroll 8
    for (int r = 0; r < CHUNK; r++) {
        m = fmaxf(m, p[(size_t)r * D]);
        q[(size_t)r * D] = m;
    }
}

// ============================================================
// GEMM: g_cp[t][i] = sum_j ce[t][j] * W[i][D + j] + b[i]
// f32x2 packed FFMA.
// ============================================================
#define GT 128
#define GI 128
#define GK 8
#define GPAD 4

__global__ __launch_bounds__(256) void gemm_ctx_kernel(
    const float* __restrict__ A,
    const float* __restrict__ W,
    const float* __restrict__ bias)
{
    __shared__ float As[GK][GT + GPAD];
    __shared__ float Bs[GK][GI + GPAD];

    int tid = threadIdx.x;
    int tx = tid & 15;
    int ty = tid >> 4;
    int i0 = blockIdx.x * GI;
    int t0 = blockIdx.y * GT;

    int lr = tid >> 1;
    int lk = (tid & 1) * 4;

    const float* Ap = A + (size_t)(t0 + lr) * D + lk;
    const float* Bp = W + (size_t)(i0 + lr) * WSTRIDE + D + lk;

    ull acc[8][4];
#pragma unroll
    for (int m = 0; m < 8; m++)
#pragma unroll
        for (int n = 0; n < 4; n++) acc[m][n] = 0ULL;

    float4 ra = *(const float4*)Ap;
    float4 rb = *(const float4*)Bp;

    for (int kk = 0; kk < D; kk += GK) {
        As[lk + 0][lr] = ra.x; As[lk + 1][lr] = ra.y;
        As[lk + 2][lr] = ra.z; As[lk + 3][lr] = ra.w;
        Bs[lk + 0][lr] = rb.x; Bs[lk + 1][lr] = rb.y;
        Bs[lk + 2][lr] = rb.z; Bs[lk + 3][lr] = rb.w;
        __syncthreads();

        if (kk + GK < D) {
            ra = *(const float4*)(Ap + kk + GK);
            rb = *(const float4*)(Bp + kk + GK);
        }

#pragma unroll
        for (int k = 0; k < GK; k++) {
            float4 a0 = *(const float4*)&As[k][ty * 8];
            float4 a1 = *(const float4*)&As[k][ty * 8 + 4];
            float4 b0 = *(const float4*)&Bs[k][tx * 8];
            float4 b1 = *(const float4*)&Bs[k][tx * 8 + 4];
            ull bp[4] = {pack2f(b0.x, b0.y), pack2f(b0.z, b0.w),
                         pack2f(b1.x, b1.y), pack2f(b1.z, b1.w)};
            ull ad[8] = {dup2f(a0.x), dup2f(a0.y), dup2f(a0.z), dup2f(a0.w),
                         dup2f(a1.x), dup2f(a1.y), dup2f(a1.z), dup2f(a1.w)};
#pragma unroll
            for (int m = 0; m < 8; m++)
#pragma unroll
                for (int n = 0; n < 4; n++)
                    acc[m][n] = ffma2(ad[m], bp[n], acc[m][n]);
        }
        __syncthreads();
    }

    float bv[8];
#pragma unroll
    for (int n = 0; n < 8; n++) bv[n] = bias[i0 + tx * 8 + n];

#pragma unroll
    for (int m = 0; m < 8; m++) {
        size_t row = (size_t)(t0 + ty * 8 + m) * D + i0 + tx * 8;
        float2 c0 = unpack2(acc[m][0]), c1 = unpack2(acc[m][1]);
        float2 c2 = unpack2(acc[m][2]), c3 = unpack2(acc[m][3]);
        float4 o0 = make_float4(c0.x + bv[0], c0.y + bv[1],
                                c1.x + bv[2], c1.y + bv[3]);
        float4 o1 = make_float4(c2.x + bv[4], c2.y + bv[5],
                                c3.x + bv[6], c3.y + bv[7]);
        *(float4*)&g_cp[row]     = o0;
        *(float4*)&g_cp[row + 4] = o1;
    }
}

// ============================================================
// Recurrence v7: segment-pipelined. 128 CTAs x 512 threads (16 warps).
// State row is 128 segments of 16 cols; segment p is produced by CTA p.
// Warp w owns segments [w*8, w*8+8) and processes each as soon as its
// producer's flag (one L2 line each) reaches t — the chip barrier is
// OFF the critical path; only the last-arriving segment is serial.
// Lane: r = lane & 15 (row i0+r), h = lane >> 4 (col half, 8 cols).
// Per segment: 16 lanes broadcast-load 32B, 4 ffma2/lane.
// Finalize: halves via shfl, s_red[buf][r*17+w] (conflict-free), one
// __syncthreads, 16 lanes reduce+sigmoid+store, lane0 release-store.
// ============================================================
__global__ __launch_bounds__(REC_THREADS, 1) void recurrence_kernel(
    const float* __restrict__ W,
    float* out)
{
    __shared__ float s_red[2][16 * 17];   // [buf][row*17 + warp]

    int tid  = threadIdx.x;
    int lane = tid & 31;
    int w    = tid >> 5;          // warp id, owns segments w*8 .. w*8+7
    int r    = lane & 15;         // row within CTA slice
    int h    = lane >> 4;         // column half within segment
    int cta  = blockIdx.x;
    int i0   = cta * ROWS_PER_CTA;
    int segbase = w * 8;          // first owned segment (== producer CTA id)

    // ---- preload W: for row i0+r, 8 cols per owned segment ----
    // wreg[s][0..3]: W[i0+r][(segbase+s)*16 + h*8 .. +7] as f32x2 pairs
    ull wreg[8][4];
#pragma unroll
    for (int s = 0; s < 8; s++) {
        const float* wp = W + (size_t)(i0 + r) * WSTRIDE
                        + (segbase + s) * 16 + h * 8;
        uint4 q0 = *(const uint4*)(wp);
        uint4 q1 = *(const uint4*)(wp + 4);
        wreg[s][0] = pack2(q0.x, q0.y);
        wreg[s][1] = pack2(q0.z, q0.w);
        wreg[s][2] = pack2(q1.x, q1.y);
        wreg[s][3] = pack2(q1.z, q1.w);
    }

    for (int t = 0; t < S; t++) {
        // prefetch hc/cp for finalize lanes (in flight during polling)
        float hcv = 0.0f, cpv = 0.0f;
        if (tid < ROWS_PER_CTA) {
            hcv = __ldg(&g_hc[(size_t)t * D + i0 + tid]);
            cpv = __ldg(&g_cp[(size_t)t * D + i0 + tid]);
        }

        ull acc0 = 0, acc1 = 0;

        if (t == 0) {
            // state = -1 everywhere: acc = -(sum of weights)
            const ull m1 = dup2f(-1.0f);
#pragma unroll
            for (int s = 0; s < 8; s++) {
                acc0 = ffma2(wreg[s][0], m1, acc0);
                acc1 = ffma2(wreg[s][1], m1, acc1);
                acc0 = ffma2(wreg[s][2], m1, acc0);
                acc1 = ffma2(wreg[s][3], m1, acc1);
            }
        } else {
            const float* srow = out + (size_t)(t - 1) * D;
            unsigned pend = 0xFFu;
            do {
                int f = 0;
                if (lane < 8)
                    f = ld_acquire_gpu(&g_flagv[(segbase + lane) * FLAG_STRIDE]);
                unsigned ready = __ballot_sync(0xFFFFFFFFu, (lane < 8) && (f >= t));
                unsigned avail = ready & pend;
                if (avail) {
                    __syncwarp();   // propagate poller lanes' acquire to all lanes
                    do {
                        int s = __ffs(avail) - 1;
                        avail &= avail - 1;
                        pend  &= ~(1u << s);
                        const float* p = srow + (segbase + s) * 16 + h * 8;
                        uint4 v0 = *(const uint4*)(p);
                        uint4 v1 = *(const uint4*)(p + 4);
                        acc0 = ffma2(wreg[s][0], pack2(v0.x, v0.y), acc0);
                        acc1 = ffma2(wreg[s][1], pack2(v0.z, v0.w), acc1);
                        acc0 = ffma2(wreg[s][2], pack2(v1.x, v1.y), acc0);
                        acc1 = ffma2(wreg[s][3], pack2(v1.z, v1.w), acc1);
                    } while (avail);
                }
            } while (pend);
        }

        // ---- combine: pair-sum, then merge column halves (lane^16) ----
        float2 fa = unpack2(acc0), fb = unpack2(acc1);
        float part = (fa.x + fa.y) + (fb.x + fb.y);
        part += __shfl_xor_sync(0xFFFFFFFFu, part, 16);

        int buf = t & 1;
        if (lane < 16)
            s_red[buf][r * 17 + w] = part;   // banks distinct for r=0..15
        __syncthreads();

        // ---- finalize: 16 lanes of warp 0 ----
        if (tid < ROWS_PER_CTA) {
            const float* rr = &s_red[buf][tid * 17];
            float s = 0.0f;
#pragma unroll
            for (int k = 0; k < 16; k++) s += rr[k];
            float x  = s + cpv;
            float g  = 1.0f / (1.0f + __expf(-x));
            float ns = hcv * g;
            __stcg(&out[(size_t)t * D + i0 + tid], ns);
            if (t == S - 1) __stcg(&out[(size_t)S * D + i0 + tid], ns);
            __syncwarp(0x0000FFFFu);   // all 16 row stores done
            if (tid == 0)
                st_release_gpu(&g_flagv[cta * FLAG_STRIDE], t + 1);
        }
        // s_red[buf] reuse at t+2 is safe without a second barrier:
        // our finalize read of buf at t precedes our release (t+1);
        // any producer P's publish of t+2 requires P's step t+1, which
        // required our flag >= t+1; our warps only write buf again at
        // t+2 after seeing P's flag >= t+2. Chain: read -> our release
        // -> P's step t+1 -> P's release t+2 -> our write. 
    }
}

// ============================================================
extern "C" void kernel_launch(void* const* d_in, const int* in_sizes, int n_in,
                              void* d_out, int out_size) {
    const float* ce = (const float*)d_in[0];   // (S, D)
    const float* W  = (const float*)d_in[1];   // (D, 2D)
    const float* b  = (const float*)d_in[2];   // (D,)
    float* out = (float*)d_out;                // (S*D + D) floats

    zero_flags_kernel<<<(NCTA_REC * FLAG_STRIDE + 1023) / 1024, 1024>>>();

    dim3 cgrid(D / 256, NCHUNK);
    cummax_chunk_kernel<<<cgrid, 256>>>(ce);
    cummax_scan_kernel<<<D / 256, 256>>>();
    cummax_write_kernel<<<cgrid, 256>>>(ce);

    dim3 ggrid(D / GI, S / GT);
    gemm_ctx_kernel<<<ggrid, 256>>>(ce, W, b);

    recurrence_kernel<<<NCTA_REC, REC_THREADS>>>(W, out);
}

// round 10
// speedup vs baseline: 1.0980x; 1.0980x over previous
#include <cuda_runtime.h>
#include <math.h>

#define S 8192
#define D 2048
#define WSTRIDE 4096           // W row stride (2*D)
#define NCTA_REC 128
#define ROWS_PER_CTA 16        // D / NCTA_REC
#define NCHUNK 64
#define CHUNK 128              // S / NCHUNK
#define REC_THREADS 512
#define FLAG_STRIDE 32         // ints; one 128B L2 line per flag
#define PF_DIST 8              // hc/cp prefetch distance (steps)

typedef unsigned long long ull;

// ---- scratch (no runtime allocation allowed) ----
__device__ float g_hc[(size_t)S * D];        // cummax result
__device__ float g_cp[(size_t)S * D];        // ctx_proj result
__device__ float g_chunkmax[NCHUNK * D];     // cummax phase-B scratch
__device__ int   g_flagv[NCTA_REC * FLAG_STRIDE];  // 1 line per flag

#define NEG_INF __int_as_float(0xff800000)

// ---- packed f32x2 helpers ----
__device__ __forceinline__ ull ffma2(ull a, ull b, ull c) {
    ull d;
    asm("fma.rn.f32x2 %0, %1, %2, %3;" : "=l"(d) : "l"(a), "l"(b), "l"(c));
    return d;
}
__device__ __forceinline__ ull pack2(unsigned int lo, unsigned int hi) {
    ull v;
    asm("mov.b64 %0, {%1, %2};" : "=l"(v) : "r"(lo), "r"(hi));
    return v;
}
__device__ __forceinline__ ull pack2f(float x, float y) {
    ull v;
    asm("mov.b64 %0, {%1, %2};" : "=l"(v) : "f"(x), "f"(y));
    return v;
}
__device__ __forceinline__ ull dup2f(float x) {
    ull v;
    asm("mov.b64 %0, {%1, %1};" : "=l"(v) : "f"(x));
    return v;
}
__device__ __forceinline__ float2 unpack2(ull v) {
    float2 r;
    asm("mov.b64 {%0, %1}, %2;" : "=f"(r.x), "=f"(r.y) : "l"(v));
    return r;
}

// ---- fence-free acquire/release primitives (NO atomics) ----
__device__ __forceinline__ int ld_acquire_gpu(const int* p) {
    int v;
    asm volatile("ld.acquire.gpu.global.s32 %0, [%1];" : "=r"(v) : "l"(p) : "memory");
    return v;
}
__device__ __forceinline__ void st_release_gpu(int* p, int v) {
    asm volatile("st.release.gpu.global.s32 [%0], %1;" :: "l"(p), "r"(v) : "memory");
}
__device__ __forceinline__ void prefetch_l2(const void* p) {
    asm volatile("prefetch.global.L2 [%0];" :: "l"(p));
}

// ============================================================
// flag reset (graph replays must start from zeroed counters)
// ============================================================
__global__ void zero_flags_kernel() {
    int idx = blockIdx.x * blockDim.x + threadIdx.x;
    if (idx < NCTA_REC * FLAG_STRIDE) g_flagv[idx] = 0;
}

// ============================================================
// cummax phase A: per-(chunk, col) max
// ============================================================
__global__ void cummax_chunk_kernel(const float* __restrict__ ce) {
    int col = blockIdx.x * blockDim.x + threadIdx.x;
    int chunk = blockIdx.y;
    const float* p = ce + (size_t)chunk * CHUNK * D + col;
    float m = NEG_INF;
#pragma unroll 8
    for (int r = 0; r < CHUNK; r++) {
        m = fmaxf(m, p[(size_t)r * D]);
    }
    g_chunkmax[chunk * D + col] = m;
}

// ============================================================
// cummax phase B: exclusive prefix-max over chunks, per column
// ============================================================
__global__ void cummax_scan_kernel() {
    int col = blockIdx.x * blockDim.x + threadIdx.x;
    float run = NEG_INF;
    for (int ch = 0; ch < NCHUNK; ch++) {
        float v = g_chunkmax[ch * D + col];
        g_chunkmax[ch * D + col] = run;   // exclusive prefix
        run = fmaxf(run, v);
    }
}

// ============================================================
// cummax phase C: inclusive scan within chunk seeded by prefix
// ============================================================
__global__ void cummax_write_kernel(const float* __restrict__ ce) {
    int col = blockIdx.x * blockDim.x + threadIdx.x;
    int chunk = blockIdx.y;
    float m = g_chunkmax[chunk * D + col];
    const float* p = ce + (size_t)chunk * CHUNK * D + col;
    float*       q = g_hc + (size_t)chunk * CHUNK * D + col;
#pragma unroll 8
    for (int r = 0; r < CHUNK; r++) {
        m = fmaxf(m, p[(size_t)r * D]);
        q[(size_t)r * D] = m;
    }
}

// ============================================================
// GEMM: g_cp[t][i] = sum_j ce[t][j] * W[i][D + j] + b[i]
// f32x2 packed FFMA.
// ============================================================
#define GT 128
#define GI 128
#define GK 8
#define GPAD 4

__global__ __launch_bounds__(256) void gemm_ctx_kernel(
    const float* __restrict__ A,
    const float* __restrict__ W,
    const float* __restrict__ bias)
{
    __shared__ float As[GK][GT + GPAD];
    __shared__ float Bs[GK][GI + GPAD];

    int tid = threadIdx.x;
    int tx = tid & 15;
    int ty = tid >> 4;
    int i0 = blockIdx.x * GI;
    int t0 = blockIdx.y * GT;

    int lr = tid >> 1;
    int lk = (tid & 1) * 4;

    const float* Ap = A + (size_t)(t0 + lr) * D + lk;
    const float* Bp = W + (size_t)(i0 + lr) * WSTRIDE + D + lk;

    ull acc[8][4];
#pragma unroll
    for (int m = 0; m < 8; m++)
#pragma unroll
        for (int n = 0; n < 4; n++) acc[m][n] = 0ULL;

    float4 ra = *(const float4*)Ap;
    float4 rb = *(const float4*)Bp;

    for (int kk = 0; kk < D; kk += GK) {
        As[lk + 0][lr] = ra.x; As[lk + 1][lr] = ra.y;
        As[lk + 2][lr] = ra.z; As[lk + 3][lr] = ra.w;
        Bs[lk + 0][lr] = rb.x; Bs[lk + 1][lr] = rb.y;
        Bs[lk + 2][lr] = rb.z; Bs[lk + 3][lr] = rb.w;
        __syncthreads();

        if (kk + GK < D) {
            ra = *(const float4*)(Ap + kk + GK);
            rb = *(const float4*)(Bp + kk + GK);
        }

#pragma unroll
        for (int k = 0; k < GK; k++) {
            float4 a0 = *(const float4*)&As[k][ty * 8];
            float4 a1 = *(const float4*)&As[k][ty * 8 + 4];
            float4 b0 = *(const float4*)&Bs[k][tx * 8];
            float4 b1 = *(const float4*)&Bs[k][tx * 8 + 4];
            ull bp[4] = {pack2f(b0.x, b0.y), pack2f(b0.z, b0.w),
                         pack2f(b1.x, b1.y), pack2f(b1.z, b1.w)};
            ull ad[8] = {dup2f(a0.x), dup2f(a0.y), dup2f(a0.z), dup2f(a0.w),
                         dup2f(a1.x), dup2f(a1.y), dup2f(a1.z), dup2f(a1.w)};
#pragma unroll
            for (int m = 0; m < 8; m++)
#pragma unroll
                for (int n = 0; n < 4; n++)
                    acc[m][n] = ffma2(ad[m], bp[n], acc[m][n]);
        }
        __syncthreads();
    }

    float bv[8];
#pragma unroll
    for (int n = 0; n < 8; n++) bv[n] = bias[i0 + tx * 8 + n];

#pragma unroll
    for (int m = 0; m < 8; m++) {
        size_t row = (size_t)(t0 + ty * 8 + m) * D + i0 + tx * 8;
        float2 c0 = unpack2(acc[m][0]), c1 = unpack2(acc[m][1]);
        float2 c2 = unpack2(acc[m][2]), c3 = unpack2(acc[m][3]);
        float4 o0 = make_float4(c0.x + bv[0], c0.y + bv[1],
                                c1.x + bv[2], c1.y + bv[3]);
        float4 o1 = make_float4(c2.x + bv[4], c2.y + bv[5],
                                c3.x + bv[6], c3.y + bv[7]);
        *(float4*)&g_cp[row]     = o0;
        *(float4*)&g_cp[row + 4] = o1;
    }
}

// ============================================================
// Recurrence v8: v6 structure with a de-serialized wait path.
// 128 CTAs x 512 threads. c = tid & 127 owns 16 state cols,
// rgrp = tid >> 7 owns 4 rows. W slice in regs (f32x2).
// Wait:  warps 0-3 poll; EACH LANE spins on ONE flag (its own 128B
//        line) with a single un-chained ld.acquire per iteration;
//        __syncthreads joins + propagates ordering CTA-wide.
// Publish: one st.release.gpu per CTA to its private line.
// hc/cp: L2-prefetched PF_DIST steps ahead (1 line each per CTA).
// ============================================================
__global__ __launch_bounds__(REC_THREADS, 1) void recurrence_kernel(
    const float* __restrict__ W,
    float* out)
{
    __shared__ float s_red[2][16 * 4];   // [buf][row*4 + colpart]

    int tid  = threadIdx.x;
    int lane = tid & 31;
    int wrp  = tid >> 5;          // 0..15
    int c    = tid & 127;         // column segment
    int rgrp = tid >> 7;          // 0..3
    int wq   = wrp & 3;           // colpart within reduction
    int cta  = blockIdx.x;
    int i0   = cta * ROWS_PER_CTA;

    // ---- preload W slice as f32x2 pairs ----
    ull w2[4][8];
#pragma unroll
    for (int m = 0; m < 4; m++) {
        const float* wp = W + (size_t)(i0 + rgrp * 4 + m) * WSTRIDE + c * 16;
#pragma unroll
        for (int j = 0; j < 4; j++) {
            uint4 q = *(const uint4*)(wp + j * 4);
            w2[m][j * 2 + 0] = pack2(q.x, q.y);
            w2[m][j * 2 + 1] = pack2(q.z, q.w);
        }
    }

    const ull minus1 = pack2(__float_as_uint(-1.0f), __float_as_uint(-1.0f));

    // warm the L2 with the first PF_DIST hc/cp lines for this CTA
    if (tid == 160) {
        for (int p = 0; p < PF_DIST; p++) {
            prefetch_l2(&g_hc[(size_t)p * D + i0]);
            prefetch_l2(&g_cp[(size_t)p * D + i0]);
        }
    }

    for (int t = 0; t < S; t++) {
        // hc/cp loads for finalize lanes (L2-hot via prefetch pipeline)
        float hcv = 0.0f, cpv = 0.0f;
        if (tid < ROWS_PER_CTA) {
            hcv = __ldg(&g_hc[(size_t)t * D + i0 + tid]);
            cpv = __ldg(&g_cp[(size_t)t * D + i0 + tid]);
        }
        // keep L2 PF_DIST steps ahead (2 lines per CTA per step)
        if (tid == 160 && t + PF_DIST < S) {
            prefetch_l2(&g_hc[(size_t)(t + PF_DIST) * D + i0]);
            prefetch_l2(&g_cp[(size_t)(t + PF_DIST) * D + i0]);
        }

        // ---- wait until ALL 128 CTAs have published row t-1 ----
        // warps 0-3: lane (wrp*32 + lane) spins on flag of CTA (wrp*32+lane)
        if (t > 0 && wrp < 4) {
            const int* fp = g_flagv + (wrp * 32 + lane) * FLAG_STRIDE;
            while (ld_acquire_gpu(fp) < t) { }
        }
        __syncthreads();   // join pollers + propagate acquire ordering

        // ---- obtain state segment (plain cached loads) ----
        ull sp[8];
        if (t == 0) {
#pragma unroll
            for (int j = 0; j < 8; j++) sp[j] = minus1;
        } else {
            const float* src = out + (size_t)(t - 1) * D + c * 16;
#pragma unroll
            for (int j = 0; j < 4; j++) {
                uint4 q = *(const uint4*)(src + j * 4);
                sp[j * 2 + 0] = pack2(q.x, q.y);
                sp[j * 2 + 1] = pack2(q.z, q.w);
            }
        }

        // ---- 4-row x 16-col partial matvec, packed f32x2 ----
        ull a0 = 0, a1 = 0, a2 = 0, a3 = 0;
#pragma unroll
        for (int j = 0; j < 8; j++) {
            a0 = ffma2(w2[0][j], sp[j], a0);
            a1 = ffma2(w2[1][j], sp[j], a1);
            a2 = ffma2(w2[2][j], sp[j], a2);
            a3 = ffma2(w2[3][j], sp[j], a3);
        }
        float2 f0 = unpack2(a0), f1 = unpack2(a1),
               f2 = unpack2(a2), f3 = unpack2(a3);
        float r0 = f0.x + f0.y;
        float r1 = f1.x + f1.y;
        float r2 = f2.x + f2.y;
        float r3 = f3.x + f3.y;

        // ---- warp shuffle reduction over 32 column segments ----
#pragma unroll
        for (int off = 16; off > 0; off >>= 1) {
            r0 += __shfl_xor_sync(0xFFFFFFFFu, r0, off);
            r1 += __shfl_xor_sync(0xFFFFFFFFu, r1, off);
            r2 += __shfl_xor_sync(0xFFFFFFFFu, r2, off);
            r3 += __shfl_xor_sync(0xFFFFFFFFu, r3, off);
        }
        int buf = t & 1;
        if (lane == 0) {
            int rb = rgrp * 4;
            s_red[buf][(rb + 0) * 4 + wq] = r0;
            s_red[buf][(rb + 1) * 4 + wq] = r1;
            s_red[buf][(rb + 2) * 4 + wq] = r2;
            s_red[buf][(rb + 3) * 4 + wq] = r3;
        }
        __syncthreads();

        // ---- finalize: 16 lanes of warp 0, then release-store the flag ----
        if (tid < ROWS_PER_CTA) {
            float4 v = *(const float4*)&s_red[buf][tid * 4];
            float s = (v.x + v.y) + (v.z + v.w);
            float x  = s + cpv;
            float g  = 1.0f / (1.0f + __expf(-x));
            float ns = hcv * g;
            __stcg(&out[(size_t)t * D + i0 + tid], ns);
            if (t == S - 1) __stcg(&out[(size_t)S * D + i0 + tid], ns);
            __syncwarp(0x0000FFFFu);   // all 16 row stores done
            if (tid == 0)
                st_release_gpu(&g_flagv[cta * FLAG_STRIDE], t + 1);
        }
        // s_red reuse at t+1 is safe: writes at t+1 occur after the t+1
        // top-of-loop __syncthreads, which follows every reader's access.
    }
}

// ============================================================
extern "C" void kernel_launch(void* const* d_in, const int* in_sizes, int n_in,
                              void* d_out, int out_size) {
    const float* ce = (const float*)d_in[0];   // (S, D)
    const float* W  = (const float*)d_in[1];   // (D, 2D)
    const float* b  = (const float*)d_in[2];   // (D,)
    float* out = (float*)d_out;                // (S*D + D) floats

    zero_flags_kernel<<<(NCTA_REC * FLAG_STRIDE + 1023) / 1024, 1024>>>();

    dim3 cgrid(D / 256, NCHUNK);
    cummax_chunk_kernel<<<cgrid, 256>>>(ce);
    cummax_scan_kernel<<<D / 256, 256>>>();
    cummax_write_kernel<<<cgrid, 256>>>(ce);

    dim3 ggrid(D / GI, S / GT);
    gemm_ctx_kernel<<<ggrid, 256>>>(ce, W, b);

    recurrence_kernel<<<NCTA_REC, REC_THREADS>>>(W, out);
}

// round 11
// speedup vs baseline: 1.3939x; 1.2695x over previous
#include <cuda_runtime.h>
#include <math.h>

#define S 8192
#define D 2048
#define WSTRIDE 4096           // W row stride (2*D)
#define NCTA_REC 128
#define ROWS_PER_CTA 16        // D / NCTA_REC
#define NCHUNK 64
#define CHUNK 128              // S / NCHUNK
#define REC_THREADS 512
#define FLAG_STRIDE 32         // ints; one 128B L2 line per flag

typedef unsigned long long ull;

// ---- scratch (no runtime allocation allowed) ----
__device__ float g_hc[(size_t)S * D];        // cummax result
__device__ float g_cp[(size_t)S * D];        // ctx_proj result
__device__ float g_chunkmax[NCHUNK * D];     // per-chunk column maxes
__device__ int   g_flagv[NCTA_REC * FLAG_STRIDE];  // per-CTA flags, 1 line each
__device__ int   g_master[FLAG_STRIDE];      // aggregated step counter (1 line)

#define NEG_INF __int_as_float(0xff800000)

// ---- packed f32x2 helpers ----
__device__ __forceinline__ ull ffma2(ull a, ull b, ull c) {
    ull d;
    asm("fma.rn.f32x2 %0, %1, %2, %3;" : "=l"(d) : "l"(a), "l"(b), "l"(c));
    return d;
}
__device__ __forceinline__ ull pack2(unsigned int lo, unsigned int hi) {
    ull v;
    asm("mov.b64 %0, {%1, %2};" : "=l"(v) : "r"(lo), "r"(hi));
    return v;
}
__device__ __forceinline__ ull pack2f(float x, float y) {
    ull v;
    asm("mov.b64 %0, {%1, %2};" : "=l"(v) : "f"(x), "f"(y));
    return v;
}
__device__ __forceinline__ ull dup2f(float x) {
    ull v;
    asm("mov.b64 %0, {%1, %1};" : "=l"(v) : "f"(x));
    return v;
}
__device__ __forceinline__ float2 unpack2(ull v) {
    float2 r;
    asm("mov.b64 {%0, %1}, %2;" : "=f"(r.x), "=f"(r.y) : "l"(v));
    return r;
}

// ---- fence-free acquire/release primitives (NO atomics) ----
__device__ __forceinline__ int ld_acquire_gpu(const int* p) {
    int v;
    asm volatile("ld.acquire.gpu.global.s32 %0, [%1];" : "=r"(v) : "l"(p) : "memory");
    return v;
}
__device__ __forceinline__ void st_release_gpu(int* p, int v) {
    asm volatile("st.release.gpu.global.s32 [%0], %1;" :: "l"(p), "r"(v) : "memory");
}

// ============================================================
// K1: cummax phase A (per-chunk column max) + flag/master reset.
// grid (D/256, NCHUNK), block 256. Block (0,0) also zeroes the
// sync state (graph replays must restart from zeroed counters).
// ============================================================
__global__ void cummax_chunk_kernel(const float* __restrict__ ce) {
    int tid = threadIdx.x;
    if (blockIdx.x == 0 && blockIdx.y == 0) {
        for (int i = tid; i < NCTA_REC * FLAG_STRIDE; i += 256) g_flagv[i] = 0;
        if (tid < FLAG_STRIDE) g_master[tid] = 0;
    }
    int col = blockIdx.x * blockDim.x + tid;
    int chunk = blockIdx.y;
    const float* p = ce + (size_t)chunk * CHUNK * D + col;
    float m = NEG_INF;
#pragma unroll 8
    for (int r = 0; r < CHUNK; r++) {
        m = fmaxf(m, p[(size_t)r * D]);
    }
    g_chunkmax[chunk * D + col] = m;
}

// ============================================================
// K2: cummax finish — per-block: rebuild the exclusive chunk prefix
// from g_chunkmax (L2-hot), then inclusive-scan own chunk into g_hc.
// grid (D/256, NCHUNK), block 256.
// ============================================================
__global__ void cummax_finish_kernel(const float* __restrict__ ce) {
    int col = blockIdx.x * blockDim.x + threadIdx.x;
    int chunk = blockIdx.y;
    float m = NEG_INF;
#pragma unroll 8
    for (int ch = 0; ch < chunk; ch++)
        m = fmaxf(m, g_chunkmax[ch * D + col]);
    const float* p = ce + (size_t)chunk * CHUNK * D + col;
    float*       q = g_hc + (size_t)chunk * CHUNK * D + col;
#pragma unroll 8
    for (int r = 0; r < CHUNK; r++) {
        m = fmaxf(m, p[(size_t)r * D]);
        q[(size_t)r * D] = m;
    }
}

// ============================================================
// K3: GEMM: g_cp[t][i] = sum_j ce[t][j] * W[i][D + j] + b[i]
// f32x2 packed FFMA.
// ============================================================
#define GT 128
#define GI 128
#define GK 8
#define GPAD 4

__global__ __launch_bounds__(256) void gemm_ctx_kernel(
    const float* __restrict__ A,
    const float* __restrict__ W,
    const float* __restrict__ bias)
{
    __shared__ float As[GK][GT + GPAD];
    __shared__ float Bs[GK][GI + GPAD];

    int tid = threadIdx.x;
    int tx = tid & 15;
    int ty = tid >> 4;
    int i0 = blockIdx.x * GI;
    int t0 = blockIdx.y * GT;

    int lr = tid >> 1;
    int lk = (tid & 1) * 4;

    const float* Ap = A + (size_t)(t0 + lr) * D + lk;
    const float* Bp = W + (size_t)(i0 + lr) * WSTRIDE + D + lk;

    ull acc[8][4];
#pragma unroll
    for (int m = 0; m < 8; m++)
#pragma unroll
        for (int n = 0; n < 4; n++) acc[m][n] = 0ULL;

    float4 ra = *(const float4*)Ap;
    float4 rb = *(const float4*)Bp;

    for (int kk = 0; kk < D; kk += GK) {
        As[lk + 0][lr] = ra.x; As[lk + 1][lr] = ra.y;
        As[lk + 2][lr] = ra.z; As[lk + 3][lr] = ra.w;
        Bs[lk + 0][lr] = rb.x; Bs[lk + 1][lr] = rb.y;
        Bs[lk + 2][lr] = rb.z; Bs[lk + 3][lr] = rb.w;
        __syncthreads();

        if (kk + GK < D) {
            ra = *(const float4*)(Ap + kk + GK);
            rb = *(const float4*)(Bp + kk + GK);
        }

#pragma unroll
        for (int k = 0; k < GK; k++) {
            float4 a0 = *(const float4*)&As[k][ty * 8];
            float4 a1 = *(const float4*)&As[k][ty * 8 + 4];
            float4 b0 = *(const float4*)&Bs[k][tx * 8];
            float4 b1 = *(const float4*)&Bs[k][tx * 8 + 4];
            ull bp[4] = {pack2f(b0.x, b0.y), pack2f(b0.z, b0.w),
                         pack2f(b1.x, b1.y), pack2f(b1.z, b1.w)};
            ull ad[8] = {dup2f(a0.x), dup2f(a0.y), dup2f(a0.z), dup2f(a0.w),
                         dup2f(a1.x), dup2f(a1.y), dup2f(a1.z), dup2f(a1.w)};
#pragma unroll
            for (int m = 0; m < 8; m++)
#pragma unroll
                for (int n = 0; n < 4; n++)
                    acc[m][n] = ffma2(ad[m], bp[n], acc[m][n]);
        }
        __syncthreads();
    }

    float bv[8];
#pragma unroll
    for (int n = 0; n < 8; n++) bv[n] = bias[i0 + tx * 8 + n];

#pragma unroll
    for (int m = 0; m < 8; m++) {
        size_t row = (size_t)(t0 + ty * 8 + m) * D + i0 + tx * 8;
        float2 c0 = unpack2(acc[m][0]), c1 = unpack2(acc[m][1]);
        float2 c2 = unpack2(acc[m][2]), c3 = unpack2(acc[m][3]);
        float4 o0 = make_float4(c0.x + bv[0], c0.y + bv[1],
                                c1.x + bv[2], c1.y + bv[3]);
        float4 o1 = make_float4(c2.x + bv[4], c2.y + bv[5],
                                c3.x + bv[6], c3.y + bv[7]);
        *(float4*)&g_cp[row]     = o0;
        *(float4*)&g_cp[row + 4] = o1;
    }
}

// ============================================================
// K4: Recurrence v9 = v6 data path + aggregator-tree sync.
// 128 CTAs x 512 threads. c = tid & 127 owns 16 state cols,
// rgrp = tid >> 7 owns 4 rows. W slice in regs (f32x2).
// Sync: producers release own flag (own L2 line). CTA 0's warps 0-3
// (128 lanes, one flag each) detect all >= t, __syncthreads, tid0
// release-stores g_master = t. Other CTAs: tid0 spins on g_master
// only. Total polling lanes chip-wide ~255 (vs 4096 in v6).
// HB chain: producer release -> CTA0 acquire -> bar -> master release
// -> consumer acquire -> bar -> state loads. Transitive.
// ============================================================
__global__ __launch_bounds__(REC_THREADS, 1) void recurrence_kernel(
    const float* __restrict__ W,
    float* out)
{
    __shared__ float s_red[2][16 * 4];   // [buf][row*4 + colpart]

    int tid  = threadIdx.x;
    int lane = tid & 31;
    int wrp  = tid >> 5;          // 0..15
    int c    = tid & 127;         // column segment
    int rgrp = tid >> 7;          // 0..3
    int wq   = wrp & 3;           // colpart within reduction
    int cta  = blockIdx.x;
    int i0   = cta * ROWS_PER_CTA;

    // ---- preload W slice as f32x2 pairs ----
    ull w2[4][8];
#pragma unroll
    for (int m = 0; m < 4; m++) {
        const float* wp = W + (size_t)(i0 + rgrp * 4 + m) * WSTRIDE + c * 16;
#pragma unroll
        for (int j = 0; j < 4; j++) {
            uint4 q = *(const uint4*)(wp + j * 4);
            w2[m][j * 2 + 0] = pack2(q.x, q.y);
            w2[m][j * 2 + 1] = pack2(q.z, q.w);
        }
    }

    const ull minus1 = pack2(__float_as_uint(-1.0f), __float_as_uint(-1.0f));

    for (int t = 0; t < S; t++) {
        // hc/cp loads for finalize lanes (in flight during wait)
        float hcv = 0.0f, cpv = 0.0f;
        if (tid < ROWS_PER_CTA) {
            hcv = __ldg(&g_hc[(size_t)t * D + i0 + tid]);
            cpv = __ldg(&g_cp[(size_t)t * D + i0 + tid]);
        }

        // ---- wait for row t-1 (aggregator tree) ----
        if (t > 0) {
            if (cta == 0) {
                // aggregator: 128 lanes, one producer flag each
                if (wrp < 4) {
                    const int* fp = g_flagv + (wrp * 32 + lane) * FLAG_STRIDE;
                    while (ld_acquire_gpu(fp) < t) { }
                }
                __syncthreads();   // all acquires done, propagate CTA-wide
                if (tid == 0)
                    st_release_gpu(&g_master[0], t);   // broadcast "all ready"
            } else {
                if (tid == 0) {
                    while (ld_acquire_gpu(&g_master[0]) < t) { }
                }
                __syncthreads();   // propagate tid0's acquire CTA-wide
            }
        }

        // ---- obtain state segment (plain cached loads) ----
        ull sp[8];
        if (t == 0) {
#pragma unroll
            for (int j = 0; j < 8; j++) sp[j] = minus1;
        } else {
            const float* src = out + (size_t)(t - 1) * D + c * 16;
#pragma unroll
            for (int j = 0; j < 4; j++) {
                uint4 q = *(const uint4*)(src + j * 4);
                sp[j * 2 + 0] = pack2(q.x, q.y);
                sp[j * 2 + 1] = pack2(q.z, q.w);
            }
        }

        // ---- 4-row x 16-col partial matvec, packed f32x2 ----
        ull a0 = 0, a1 = 0, a2 = 0, a3 = 0;
#pragma unroll
        for (int j = 0; j < 8; j++) {
            a0 = ffma2(w2[0][j], sp[j], a0);
            a1 = ffma2(w2[1][j], sp[j], a1);
            a2 = ffma2(w2[2][j], sp[j], a2);
            a3 = ffma2(w2[3][j], sp[j], a3);
        }
        float2 f0 = unpack2(a0), f1 = unpack2(a1),
               f2 = unpack2(a2), f3 = unpack2(a3);
        float r0 = f0.x + f0.y;
        float r1 = f1.x + f1.y;
        float r2 = f2.x + f2.y;
        float r3 = f3.x + f3.y;

        // ---- warp shuffle reduction over 32 column segments ----
#pragma unroll
        for (int off = 16; off > 0; off >>= 1) {
            r0 += __shfl_xor_sync(0xFFFFFFFFu, r0, off);
            r1 += __shfl_xor_sync(0xFFFFFFFFu, r1, off);
            r2 += __shfl_xor_sync(0xFFFFFFFFu, r2, off);
            r3 += __shfl_xor_sync(0xFFFFFFFFu, r3, off);
        }
        int buf = t & 1;
        if (lane == 0) {
            int rb = rgrp * 4;
            s_red[buf][(rb + 0) * 4 + wq] = r0;
            s_red[buf][(rb + 1) * 4 + wq] = r1;
            s_red[buf][(rb + 2) * 4 + wq] = r2;
            s_red[buf][(rb + 3) * 4 + wq] = r3;
        }
        __syncthreads();

        // ---- finalize: 16 lanes of warp 0, then release-store the flag ----
        if (tid < ROWS_PER_CTA) {
            float4 v = *(const float4*)&s_red[buf][tid * 4];
            float s = (v.x + v.y) + (v.z + v.w);
            float x  = s + cpv;
            float g  = 1.0f / (1.0f + __expf(-x));
            float ns = hcv * g;
            __stcg(&out[(size_t)t * D + i0 + tid], ns);
            if (t == S - 1) __stcg(&out[(size_t)S * D + i0 + tid], ns);
            __syncwarp(0x0000FFFFu);   // all 16 row stores done
            if (tid == 0)
                st_release_gpu(&g_flagv[cta * FLAG_STRIDE], t + 1);
        }
        // s_red reuse at t+1 is safe: writes at t+1 occur after the t+1
        // top-of-loop __syncthreads, which follows every reader's access.
    }
}

// ============================================================
extern "C" void kernel_launch(void* const* d_in, const int* in_sizes, int n_in,
                              void* d_out, int out_size) {
    const float* ce = (const float*)d_in[0];   // (S, D)
    const float* W  = (const float*)d_in[1];   // (D, 2D)
    const float* b  = (const float*)d_in[2];   // (D,)
    float* out = (float*)d_out;                // (S*D + D) floats

    dim3 cgrid(D / 256, NCHUNK);
    cummax_chunk_kernel<<<cgrid, 256>>>(ce);    // launch 1 (+ flag reset)
    cummax_finish_kernel<<<cgrid, 256>>>(ce);   // launch 2

    dim3 ggrid(D / GI, S / GT);
    gemm_ctx_kernel<<<ggrid, 256>>>(ce, W, b);  // launch 3

    recurrence_kernel<<<NCTA_REC, REC_THREADS>>>(W, out);  // launch 4
}